// round 11
// baseline (speedup 1.0000x reference)
#include <cuda_runtime.h>
#include <cuda_fp16.h>
#include <cstdint>

#define LIB    969          // 1 + 16 + 136 + 816
#define KPAD   1024         // padded K: 16 chunks of 64
#define NODE   16
#define NT     256          // 2 threads per row (parity-split chunk building)
#define TILE_M 128

// dynamic smem layout (bytes)
#define OFF_A0 0                 // theta even chunks: 128 x 64 fp16 = 16 KB (SW128 rows)
#define OFF_A1 16384             // theta odd  chunks: 16 KB
#define OFF_B  32768             // C^T fp16: 16 chunks x (16 x 64 fp16 = 2 KB) = 32 KB
#define SMEM_TOTAL 65536         // 64 KB

typedef unsigned int u32;

__device__ __forceinline__ u32 smem_u32_of(const void* p) {
    u32 a; asm("{ .reg .u64 t; cvta.to.shared.u64 t, %1; cvt.u32.u64 %0, t; }" : "=r"(a) : "l"(p));
    return a;
}
__device__ __forceinline__ u32 swz(u32 off) { return off ^ ((off >> 3) & 0x70); }

// pack 2 fp32 -> fp16x2; result.hi = first arg, result.lo = second arg
__device__ __forceinline__ u32 f2h2(float hi, float lo) {
    u32 r; asm("cvt.rn.f16x2.f32 %0, %1, %2;" : "=r"(r) : "f"(hi), "f"(lo)); return r;
}
__device__ __forceinline__ void ldm4(u32 r[4], u32 addr) {
    asm volatile("ldmatrix.sync.aligned.m8n8.x4.shared.b16 {%0,%1,%2,%3}, [%4];"
                 : "=r"(r[0]), "=r"(r[1]), "=r"(r[2]), "=r"(r[3]) : "r"(addr));
}
__device__ __forceinline__ void hmma(float c[4], const u32 a[4], u32 b0, u32 b1) {
    asm volatile("mma.sync.aligned.m16n8k16.row.col.f32.f16.f16.f32 "
                 "{%0,%1,%2,%3}, {%4,%5,%6,%7}, {%8,%9}, {%0,%1,%2,%3};"
                 : "+f"(c[0]), "+f"(c[1]), "+f"(c[2]), "+f"(c[3])
                 : "r"(a[0]), "r"(a[1]), "r"(a[2]), "r"(a[3]), "r"(b0), "r"(b1));
}

extern __shared__ char smem[];

// Consume chunk c: warp owns m16 tile (rows 16*wid..16*wid+15), 4 k-steps, 1 product.
__device__ __forceinline__ void mma_chunk(int c, u32 sb,
                                          const u32 aoffs[4], const u32 boffs[4],
                                          float acc[2][4])
{
    const u32 aSm = sb + ((c & 1) ? OFF_A1 : OFF_A0);
    const u32 bSm = sb + OFF_B + (u32)c * 2048u;
    #pragma unroll
    for (int ks = 0; ks < 4; ks++) {
        u32 b[4], a[4];
        ldm4(b, bSm + boffs[ks]);
        ldm4(a, aSm + aoffs[ks]);
        hmma(acc[0], a, b[0], b[2]);
        hmma(acc[1], a, b[1], b[3]);
    }
}

__global__ void __launch_bounds__(NT, 2)
sindy_tc_kernel(const float* __restrict__ z,
                const float* __restrict__ coef,
                const float* __restrict__ mask,
                float* __restrict__ out, int N, int out_last)
{
    const int tid  = threadIdx.x;
    const int lane = tid & 31;
    const int wid  = tid >> 5;            // 0..7
    const int rtid = tid & (TILE_M - 1);  // row within tile
    const int par  = tid >> 7;            // chunk parity this thread builds (warp-uniform)
    const u32 sb = smem_u32_of(smem);

    // ---- build B = C^T (masked) fp16, K-major SW128, 64-wide chunks ----
    float l1p = 0.f;
    for (int e = tid; e < KPAD * NODE; e += NT) {
        const int k = e >> 4, n = e & 15;
        float v = 0.f;
        if (k < LIB) v = coef[k * NODE + n] * mask[k * NODE + n];
        l1p += fabsf(v);
        const u32 boff = (u32)(k >> 6) * 2048u + swz((u32)n * 128u + (u32)(k & 63) * 2u);
        *reinterpret_cast<__half*>(smem + OFF_B + boff) = __float2half_rn(v);
    }

    // ---- load z row (both parity threads load the same row; L1 hit) ----
    const int row = blockIdx.x * TILE_M + rtid;
    float zr[16];
    {
        const int lr = row < N ? row : N - 1;
        const float4* zp = reinterpret_cast<const float4*>(z + (size_t)lr * 16);
        #pragma unroll
        for (int q = 0; q < 4; q++) {
            float4 t = zp[q];
            zr[4*q+0] = t.x; zr[4*q+1] = t.y; zr[4*q+2] = t.z; zr[4*q+3] = t.w;
        }
    }
    __syncthreads();   // B visible

    // ---- block 0: L1 scalar (overlapped with other blocks' compute) ----
    if (blockIdx.x == 0) {
        __shared__ float red[NT / 32];
        float s = l1p;
        #pragma unroll
        for (int o = 16; o; o >>= 1) s += __shfl_xor_sync(0xFFFFFFFFu, s, o);
        if (lane == 0) red[wid] = s;
        __syncthreads();
        if (tid == 0) {
            float t = 0.f;
            #pragma unroll
            for (int w = 0; w < NT / 32; w++) t += red[w];
            out[out_last] = t / (float)(LIB * NODE);
        }
    }

    // ---- hoisted ldmatrix offsets (chunk-invariant) ----
    u32 aoffs[4], boffs[4];
    {
        const u32 aBase = (u32)(16 * wid + (lane & 7) + ((lane >> 3) & 1) * 8) * 128u
                        + ((lane >> 4) & 1) * 16u;
        const u32 bBase = (u32)((lane & 7) + ((lane >> 3) & 1) * 8) * 128u
                        + ((lane >> 4) & 1) * 16u;
        #pragma unroll
        for (int ks = 0; ks < 4; ks++) {
            aoffs[ks] = swz(aBase + (u32)ks * 32u);
            boffs[ks] = swz(bBase + (u32)ks * 32u);
        }
    }

    float acc[2][4];
    #pragma unroll
    for (int b = 0; b < 2; b++)
        #pragma unroll
        for (int q = 0; q < 4; q++) acc[b][q] = 0.f;

    // ---- fused theta build + MMA; thread builds only its parity's chunks ----
    // par=0 threads own buf A0 (even chunks), par=1 own A1 (odd chunks).
    // Timeline: ... sync -> MMA(c) reads buf[c&1] ; build(c+1) writes buf[~c&1] -> sync ...
    // buf[c&1] rewritten first at build(c+2), strictly after the next sync. Safe.
    const u32 aDstOff = par ? OFF_A1 : OFF_A0;      // BYTE OFFSET into generic smem ptr
    const u32 rowbase = (u32)rtid * 128u;
    float fb[8];
    int fcnt = 0;

#define FLUSH8() do {                                                                  \
        u32 h0 = f2h2(fb[1], fb[0]), h1 = f2h2(fb[3], fb[2]);                          \
        u32 h2 = f2h2(fb[5], fb[4]), h3 = f2h2(fb[7], fb[6]);                          \
        const u32 aoff = aDstOff + swz(rowbase + (u32)((fcnt >> 3) & 7) * 16u);        \
        *reinterpret_cast<uint4*>(smem + aoff) = make_uint4(h0, h1, h2, h3);           \
    } while (0)

#define EMIT(v) do {                                                                   \
        if (((fcnt >> 6) & 1) == par) {                                                \
            fb[fcnt & 7] = (v);                                                        \
            if ((fcnt & 7) == 7) FLUSH8();                                             \
        }                                                                              \
        if ((fcnt & 63) == 63) {                                                       \
            __syncthreads();                                                           \
            mma_chunk(fcnt >> 6, sb, aoffs, boffs, acc);                               \
        }                                                                              \
        fcnt++;                                                                        \
    } while (0)

    EMIT(1.0f);
    #pragma unroll
    for (int i = 0; i < 16; i++) EMIT(zr[i]);
    #pragma unroll
    for (int i = 0; i < 16; i++)
        #pragma unroll
        for (int j = i; j < 16; j++) EMIT(zr[i] * zr[j]);
    #pragma unroll
    for (int i = 0; i < 16; i++)
        #pragma unroll
        for (int j = i; j < 16; j++) {
            const float p = zr[i] * zr[j];
            #pragma unroll
            for (int k = j; k < 16; k++) EMIT(p * zr[k]);
        }
    #pragma unroll
    for (int t = 0; t < KPAD - LIB; t++) EMIT(0.0f);
    // fcnt == 1024: all 16 chunks built and consumed

    // ---- write fragments: warp w rows 16w+g(+8), cols 8nt+2t(+1) ----
    const int rbase = blockIdx.x * TILE_M + 16 * wid;
    const int g = lane >> 2, t2 = 2 * (lane & 3);
    #pragma unroll
    for (int half = 0; half < 2; half++) {
        const int r = rbase + g + half * 8;
        if (r < N) {
            #pragma unroll
            for (int nt = 0; nt < 2; nt++) {
                float2 v = make_float2(acc[nt][half*2 + 0], acc[nt][half*2 + 1]);
                *reinterpret_cast<float2*>(out + (size_t)r * 16 + 8*nt + t2) = v;
            }
        }
    }

#undef EMIT
#undef FLUSH8
}

extern "C" void kernel_launch(void* const* d_in, const int* in_sizes, int n_in,
                              void* d_out, int out_size)
{
    const float* z    = (const float*)d_in[0];   // (N, 16) fp32
    const float* coef = (const float*)d_in[1];   // (969, 16) fp32
    const float* mask = (const float*)d_in[2];   // (969, 16) fp32
    float* out = (float*)d_out;

    const int N = in_sizes[0] / 16;              // 262144
    const int grid = (N + TILE_M - 1) / TILE_M;  // 2048

    cudaFuncSetAttribute(sindy_tc_kernel,
                         cudaFuncAttributeMaxDynamicSharedMemorySize, SMEM_TOTAL);

    sindy_tc_kernel<<<grid, NT, SMEM_TOTAL>>>(z, coef, mask, out, N, out_size - 1);
}

// round 12
// speedup vs baseline: 7.4377x; 7.4377x over previous
#include <cuda_runtime.h>
#include <cuda_fp16.h>
#include <cstdint>

#define LIB    969          // 1 + 16 + 136 + 816
#define KPAD   1024         // padded K: 16 chunks of 64
#define NODE   16
#define NT     128
#define TILE_M 128

// dynamic smem layout (bytes)
#define OFF_A0 0                 // theta chunk buf0: 128 x 64 fp16 = 16 KB (SW128 rows)
#define OFF_A1 16384             // theta chunk buf1: 16 KB
#define OFF_B  32768             // C^T fp16 (masked): 16 chunks x 2 KB = 32 KB
#define SMEM_TOTAL 65536         // 64 KB -> 3 CTAs/SM

typedef unsigned int u32;

__device__ __forceinline__ u32 smem_u32_of(const void* p) {
    u32 a; asm("{ .reg .u64 t; cvta.to.shared.u64 t, %1; cvt.u32.u64 %0, t; }" : "=r"(a) : "l"(p));
    return a;
}
__device__ __forceinline__ u32 swz(u32 off) { return off ^ ((off >> 3) & 0x70); }

// pack 2 fp32 -> fp16x2; result.hi = first arg, result.lo = second arg
__device__ __forceinline__ u32 f2h2(float hi, float lo) {
    u32 r; asm("cvt.rn.f16x2.f32 %0, %1, %2;" : "=r"(r) : "f"(hi), "f"(lo)); return r;
}
__device__ __forceinline__ void ldm4(u32 r[4], u32 addr) {
    asm volatile("ldmatrix.sync.aligned.m8n8.x4.shared.b16 {%0,%1,%2,%3}, [%4];"
                 : "=r"(r[0]), "=r"(r[1]), "=r"(r[2]), "=r"(r[3]) : "r"(addr));
}
__device__ __forceinline__ void hmma(float c[4], const u32 a[4], u32 b0, u32 b1) {
    asm volatile("mma.sync.aligned.m16n8k16.row.col.f32.f16.f16.f32 "
                 "{%0,%1,%2,%3}, {%4,%5,%6,%7}, {%8,%9}, {%0,%1,%2,%3};"
                 : "+f"(c[0]), "+f"(c[1]), "+f"(c[2]), "+f"(c[3])
                 : "r"(a[0]), "r"(a[1]), "r"(a[2]), "r"(a[3]), "r"(b0), "r"(b1));
}

extern __shared__ char smem[];

// Consume chunk c from buffer (c&1): 4 k-steps of m16n8k16, single product A*B.
__device__ __forceinline__ void mma_chunk(int c, int lane, int wid, u32 sb,
                                          float acc[2][2][4])
{
    const u32 aBase = (u32)(32 * wid + (lane & 7) + ((lane >> 3) & 1) * 8) * 128u
                    + ((lane >> 4) & 1) * 16u;
    const u32 bBase = (u32)((lane & 7) + ((lane >> 3) & 1) * 8) * 128u
                    + ((lane >> 4) & 1) * 16u;
    const u32 aSm = sb + ((c & 1) ? OFF_A1 : OFF_A0);
    const u32 bSm = sb + OFF_B + (u32)c * 2048u;

    #pragma unroll
    for (int ks = 0; ks < 4; ks++) {
        const u32 kb = (u32)ks * 32u;
        u32 b[4], a0[4], a1[4];
        ldm4(b, bSm + swz(bBase + kb));
        ldm4(a0, aSm + swz(aBase + kb));
        ldm4(a1, aSm + swz(aBase + 2048u + kb));   // mt=1: +16 rows * 128 B
        hmma(acc[0][0], a0, b[0], b[2]);
        hmma(acc[0][1], a0, b[1], b[3]);
        hmma(acc[1][0], a1, b[0], b[2]);
        hmma(acc[1][1], a1, b[1], b[3]);
    }
}

__global__ void __launch_bounds__(NT, 3)
sindy_tc_kernel(const float* __restrict__ z,
                const float* __restrict__ coef,
                const float* __restrict__ mask,
                float* __restrict__ out, int N, int out_last)
{
    const int tid  = threadIdx.x;
    const int lane = tid & 31;
    const int wid  = tid >> 5;
    const u32 sb = smem_u32_of(smem);

    // ---- build B = C^T (masked) fp16, K-major SW128, 64-wide chunks ----
    float l1p = 0.f;
    for (int e = tid; e < KPAD * NODE; e += NT) {
        const int k = e >> 4, n = e & 15;
        float v = 0.f;
        if (k < LIB) v = coef[k * NODE + n] * mask[k * NODE + n];
        l1p += fabsf(v);
        const u32 boff = (u32)(k >> 6) * 2048u + swz((u32)n * 128u + (u32)(k & 63) * 2u);
        *reinterpret_cast<__half*>(smem + OFF_B + boff) = __float2half_rn(v);
    }

    // ---- load z row (thread tid owns tile row tid) ----
    const int row = blockIdx.x * TILE_M + tid;
    float zr[16];
    {
        const int lr = row < N ? row : N - 1;
        const float4* zp = reinterpret_cast<const float4*>(z + (size_t)lr * 16);
        #pragma unroll
        for (int q = 0; q < 4; q++) {
            float4 t = zp[q];
            zr[4*q+0] = t.x; zr[4*q+1] = t.y; zr[4*q+2] = t.z; zr[4*q+3] = t.w;
        }
    }
    __syncthreads();   // B visible

    // ---- block 0: L1 scalar (overlapped with other blocks' compute) ----
    if (blockIdx.x == 0) {
        __shared__ float red[NT / 32];
        float s = l1p;
        #pragma unroll
        for (int o = 16; o; o >>= 1) s += __shfl_xor_sync(0xFFFFFFFFu, s, o);
        if (lane == 0) red[wid] = s;
        __syncthreads();
        if (tid == 0) {
            float t = 0.f;
            #pragma unroll
            for (int w = 0; w < NT / 32; w++) t += red[w];
            out[out_last] = t / (float)(LIB * NODE);
        }
    }

    float acc[2][2][4];
    #pragma unroll
    for (int a = 0; a < 2; a++)
        #pragma unroll
        for (int b = 0; b < 2; b++)
            #pragma unroll
            for (int q = 0; q < 4; q++) acc[a][b][q] = 0.f;

    // ---- fused theta build + MMA, 16 chunks of 64 features, double-buffered A ----
    // Timeline: sync -> MMA(c) reads buf[c&1]; build(c+1) writes buf[~c&1] -> sync ...
    // buf[c&1] rewritten first at build(c+2), strictly after the next sync. Safe.
    const u32 rowbase = (u32)tid * 128u;
    float fb[8];
    int fcnt = 0;

#define FLUSH8() do {                                                                  \
        u32 h0 = f2h2(fb[1], fb[0]), h1 = f2h2(fb[3], fb[2]);                          \
        u32 h2 = f2h2(fb[5], fb[4]), h3 = f2h2(fb[7], fb[6]);                          \
        const u32 bo = ((fcnt >> 6) & 1) ? OFF_A1 : OFF_A0;                            \
        const u32 aoff = bo + swz(rowbase + (u32)((fcnt >> 3) & 7) * 16u);             \
        *reinterpret_cast<uint4*>(smem + aoff) = make_uint4(h0, h1, h2, h3);           \
    } while (0)

#define EMIT(v) do {                                                                   \
        fb[fcnt & 7] = (v);                                                            \
        if ((fcnt & 7) == 7) FLUSH8();                                                 \
        if ((fcnt & 63) == 63) {                                                       \
            __syncthreads();                                                           \
            mma_chunk(fcnt >> 6, lane, wid, sb, acc);                                  \
        }                                                                              \
        fcnt++;                                                                        \
    } while (0)

    EMIT(1.0f);
    #pragma unroll
    for (int i = 0; i < 16; i++) EMIT(zr[i]);
    #pragma unroll
    for (int i = 0; i < 16; i++)
        #pragma unroll
        for (int j = i; j < 16; j++) EMIT(zr[i] * zr[j]);
    #pragma unroll
    for (int i = 0; i < 16; i++)
        #pragma unroll
        for (int j = i; j < 16; j++) {
            const float p = zr[i] * zr[j];
            #pragma unroll
            for (int k = j; k < 16; k++) EMIT(p * zr[k]);
        }
    #pragma unroll
    for (int t = 0; t < KPAD - LIB; t++) EMIT(0.0f);
    // fcnt == 1024: all 16 chunks built and consumed

    // ---- write fragments: warp w rows 32w+16mt+g(+8), cols 8nt+2t(+1) ----
    const int rbase = blockIdx.x * TILE_M + 32 * wid;
    const int g = lane >> 2, t2 = 2 * (lane & 3);
    #pragma unroll
    for (int mt = 0; mt < 2; mt++)
        #pragma unroll
        for (int half = 0; half < 2; half++) {
            const int r = rbase + 16 * mt + g + half * 8;
            if (r < N) {
                #pragma unroll
                for (int nt = 0; nt < 2; nt++) {
                    float2 v = make_float2(acc[mt][nt][half*2 + 0], acc[mt][nt][half*2 + 1]);
                    *reinterpret_cast<float2*>(out + (size_t)r * 16 + 8*nt + t2) = v;
                }
            }
        }

#undef EMIT
#undef FLUSH8
}

extern "C" void kernel_launch(void* const* d_in, const int* in_sizes, int n_in,
                              void* d_out, int out_size)
{
    const float* z    = (const float*)d_in[0];   // (N, 16) fp32
    const float* coef = (const float*)d_in[1];   // (969, 16) fp32
    const float* mask = (const float*)d_in[2];   // (969, 16) fp32
    float* out = (float*)d_out;

    const int N = in_sizes[0] / 16;              // 262144
    const int grid = (N + TILE_M - 1) / TILE_M;  // 2048

    cudaFuncSetAttribute(sindy_tc_kernel,
                         cudaFuncAttributeMaxDynamicSharedMemorySize, SMEM_TOTAL);

    sindy_tc_kernel<<<grid, NT, SMEM_TOTAL>>>(z, coef, mask, out, N, out_size - 1);
}